// round 3
// baseline (speedup 1.0000x reference)
#include <cuda_runtime.h>
#include <cuda_bf16.h>
#include <cstdint>

// ============================================================================
// y = x @ W_mod^T ; W_mod = W with values*0.1 scattered at flip_idx (last wins)
// x:[256,4096] f32, W:[4096,4096] f32, flip:[1M] INT32 (JAX x64 off!), vals f32
// GEMM: bf16-split 3-pass via mma.sync (base sm_103 target: no tcgen05)
// ============================================================================

#define O_DIM  4096
#define I_DIM  4096
#define B_ROWS 256
#define W_ELEMS (O_DIM * I_DIM)
#define X_ELEMS (B_ROWS * I_DIM)

__device__ __align__(16) __nv_bfloat16 g_whi[W_ELEMS];
__device__ __align__(16) __nv_bfloat16 g_wlo[W_ELEMS];
__device__ __align__(16) __nv_bfloat16 g_xhi[X_ELEMS];
__device__ __align__(16) __nv_bfloat16 g_xlo[X_ELEMS];
// zero at module load; cleanup_kernel restores the all-zero invariant each run
__device__ int g_aux[W_ELEMS];

__device__ __forceinline__ void split_bf16(float f, unsigned short& h, unsigned short& l) {
    __nv_bfloat16 hb = __float2bfloat16(f);
    float r = f - __bfloat162float(hb);
    __nv_bfloat16 lb = __float2bfloat16(r);
    h = __bfloat16_as_ushort(hb);
    l = __bfloat16_as_ushort(lb);
}

// ---------------------------------------------------------------- converts
__global__ void convert_w_kernel(const float4* __restrict__ w) {
    int i = blockIdx.x * blockDim.x + threadIdx.x;
    float4 v = w[i];
    unsigned short h0,h1,h2,h3,l0,l1,l2,l3;
    split_bf16(v.x,h0,l0); split_bf16(v.y,h1,l1);
    split_bf16(v.z,h2,l2); split_bf16(v.w,h3,l3);
    reinterpret_cast<uint2*>(g_whi)[i] =
        make_uint2((uint32_t)h0 | ((uint32_t)h1<<16), (uint32_t)h2 | ((uint32_t)h3<<16));
    reinterpret_cast<uint2*>(g_wlo)[i] =
        make_uint2((uint32_t)l0 | ((uint32_t)l1<<16), (uint32_t)l2 | ((uint32_t)l3<<16));
}

__global__ void convert_x_kernel(const float4* __restrict__ x) {
    int i = blockIdx.x * blockDim.x + threadIdx.x;
    float4 v = x[i];
    unsigned short h0,h1,h2,h3,l0,l1,l2,l3;
    split_bf16(v.x,h0,l0); split_bf16(v.y,h1,l1);
    split_bf16(v.z,h2,l2); split_bf16(v.w,h3,l3);
    reinterpret_cast<uint2*>(g_xhi)[i] =
        make_uint2((uint32_t)h0 | ((uint32_t)h1<<16), (uint32_t)h2 | ((uint32_t)h3<<16));
    reinterpret_cast<uint2*>(g_xlo)[i] =
        make_uint2((uint32_t)l0 | ((uint32_t)l1<<16), (uint32_t)l2 | ((uint32_t)l3<<16));
}

// ---------------------------------------------------- scatter, last-wins
__global__ void winner_kernel(const int* __restrict__ flip, int n) {
    int i = blockIdx.x * blockDim.x + threadIdx.x;
    if (i < n) atomicMax(&g_aux[flip[i]], i + 1);
}

__global__ void scatter_kernel(const int* __restrict__ flip,
                               const float* __restrict__ vals, int n) {
    int i = blockIdx.x * blockDim.x + threadIdx.x;
    if (i < n) {
        int pos = flip[i];
        if (g_aux[pos] == i + 1) {
            unsigned short h, l;
            split_bf16(vals[i] * 0.1f, h, l);
            g_whi[pos] = __ushort_as_bfloat16(h);
            g_wlo[pos] = __ushort_as_bfloat16(l);
        }
    }
}

__global__ void cleanup_kernel(const int* __restrict__ flip, int n) {
    int i = blockIdx.x * blockDim.x + threadIdx.x;
    if (i < n) g_aux[flip[i]] = 0;
}

// ============================================================================
// GEMM: CTA tile 128x64, K-chunk 64, double-buffered cp.async, SW128 swizzle,
// ldmatrix.x4 + mma.sync.m16n8k16 bf16->f32, 3 passes into one accumulator.
// ============================================================================
#define SW128(b) ((b) ^ (((b) >> 3) & 0x70))

static constexpr int A_HI = 0;        // 128 rows x 128B
static constexpr int A_LO = 16384;
static constexpr int B_HI = 32768;    // 64 rows x 128B
static constexpr int B_LO = 40960;
static constexpr int BUF  = 49152;
static constexpr int GEMM_SMEM = 2 * BUF;   // 96 KB
static constexpr int NC   = I_DIM / 64;     // 64 K-chunks

__device__ __forceinline__ uint32_t smem_u32(const void* p) {
    uint32_t a;
    asm("{ .reg .u64 t; cvta.to.shared.u64 t, %1; cvt.u32.u64 %0, t; }"
        : "=r"(a) : "l"(p));
    return a;
}

__device__ __forceinline__ void cp16(uint32_t dst, const void* src) {
    asm volatile("cp.async.cg.shared.global [%0], [%1], 16;"
                 :: "r"(dst), "l"(src) : "memory");
}
__device__ __forceinline__ void cp_commit() {
    asm volatile("cp.async.commit_group;" ::: "memory");
}
__device__ __forceinline__ void cp_wait0() {
    asm volatile("cp.async.wait_group 0;" ::: "memory");
}

__device__ __forceinline__ void ldsm4(uint32_t* r, uint32_t addr) {
    asm volatile("ldmatrix.sync.aligned.m8n8.x4.shared.b16 {%0,%1,%2,%3}, [%4];"
                 : "=r"(r[0]), "=r"(r[1]), "=r"(r[2]), "=r"(r[3]) : "r"(addr));
}

__device__ __forceinline__ void mma16816(float* c, const uint32_t* a,
                                         uint32_t b0, uint32_t b1) {
    asm volatile(
        "mma.sync.aligned.m16n8k16.row.col.f32.bf16.bf16.f32 "
        "{%0,%1,%2,%3}, {%4,%5,%6,%7}, {%8,%9}, {%0,%1,%2,%3};"
        : "+f"(c[0]), "+f"(c[1]), "+f"(c[2]), "+f"(c[3])
        : "r"(a[0]), "r"(a[1]), "r"(a[2]), "r"(a[3]), "r"(b0), "r"(b1));
}

__device__ __forceinline__ void prefetch(uint32_t bufb, int c, int m0, int n0, int tid) {
    if (tid < 128) {
        const uint4* sh = reinterpret_cast<const uint4*>(g_xhi) + (size_t)(m0 + tid) * 512 + c * 8;
        const uint4* sl = reinterpret_cast<const uint4*>(g_xlo) + (size_t)(m0 + tid) * 512 + c * 8;
        const uint32_t rb = (uint32_t)tid * 128;
        #pragma unroll
        for (int v = 0; v < 8; ++v) {
            const uint32_t so = SW128(rb + v * 16);
            cp16(bufb + A_HI + so, sh + v);
            cp16(bufb + A_LO + so, sl + v);
        }
    } else {
        const int r = tid - 128;
        const int row = r & 63;
        const __nv_bfloat16* g = (r < 64) ? g_whi : g_wlo;
        const uint32_t off = (r < 64) ? (uint32_t)B_HI : (uint32_t)B_LO;
        const uint4* src = reinterpret_cast<const uint4*>(g) + (size_t)(n0 + row) * 512 + c * 8;
        const uint32_t rb = (uint32_t)row * 128;
        #pragma unroll
        for (int v = 0; v < 8; ++v)
            cp16(bufb + off + SW128(rb + v * 16), src + v);
    }
}

__global__ void __launch_bounds__(256, 1) gemm_kernel(float* __restrict__ y) {
    extern __shared__ __align__(1024) char smem[];
    const uint32_t sb = smem_u32(smem);
    const int tid = threadIdx.x, lane = tid & 31, wid = tid >> 5;
    const int wm = wid >> 1, wn = wid & 1;          // warp grid 4(M) x 2(N)
    const int n0 = blockIdx.x * 64;
    const int m0 = blockIdx.y * 128;

    float acc[2][4][4];
    #pragma unroll
    for (int i = 0; i < 2; ++i)
        #pragma unroll
        for (int j = 0; j < 4; ++j)
            #pragma unroll
            for (int q = 0; q < 4; ++q) acc[i][j][q] = 0.f;

    // ldmatrix lane addressing components
    const int rl = lane & 15, kh = lane >> 4;
    const uint32_t arow0 = (uint32_t)(wm * 32 + rl) * 128;
    const uint32_t arow1 = arow0 + 16 * 128;
    const uint32_t brow0 = (uint32_t)(wn * 32 + rl) * 128;
    const uint32_t brow1 = brow0 + 16 * 128;

    prefetch(sb, 0, m0, n0, tid);
    cp_commit();

    for (int c = 0; c < NC; ++c) {
        cp_wait0();
        __syncthreads();
        if (c + 1 < NC) {
            prefetch(sb + ((c + 1) & 1) * BUF, c + 1, m0, n0, tid);
            cp_commit();
        }
        const uint32_t bb = sb + (c & 1) * BUF;

        #pragma unroll
        for (int ks = 0; ks < 4; ++ks) {
            const uint32_t kb = (uint32_t)ks * 32 + (uint32_t)kh * 16;
            uint32_t ah[2][4], al[2][4], bh[2][4], bl[2][4];
            ldsm4(ah[0], bb + A_HI + SW128(arow0 + kb));
            ldsm4(ah[1], bb + A_HI + SW128(arow1 + kb));
            ldsm4(al[0], bb + A_LO + SW128(arow0 + kb));
            ldsm4(al[1], bb + A_LO + SW128(arow1 + kb));
            ldsm4(bh[0], bb + B_HI + SW128(brow0 + kb));
            ldsm4(bh[1], bb + B_HI + SW128(brow1 + kb));
            ldsm4(bl[0], bb + B_LO + SW128(brow0 + kb));
            ldsm4(bl[1], bb + B_LO + SW128(brow1 + kb));
            #pragma unroll
            for (int mi = 0; mi < 2; ++mi)
                #pragma unroll
                for (int nj = 0; nj < 2; ++nj) {
                    mma16816(acc[mi][nj*2+0], ah[mi], bh[nj][0], bh[nj][2]);
                    mma16816(acc[mi][nj*2+1], ah[mi], bh[nj][1], bh[nj][3]);
                    mma16816(acc[mi][nj*2+0], ah[mi], bl[nj][0], bl[nj][2]);
                    mma16816(acc[mi][nj*2+1], ah[mi], bl[nj][1], bl[nj][3]);
                    mma16816(acc[mi][nj*2+0], al[mi], bh[nj][0], bh[nj][2]);
                    mma16816(acc[mi][nj*2+1], al[mi], bh[nj][1], bh[nj][3]);
                }
        }
        __syncthreads();
    }

    // Epilogue: c-frag lane l -> row (l>>2)[+8], cols (l&3)*2 + {0,1}
    #pragma unroll
    for (int mi = 0; mi < 2; ++mi) {
        const int row0 = m0 + wm * 32 + mi * 16 + (lane >> 2);
        #pragma unroll
        for (int nb = 0; nb < 4; ++nb) {
            const int col = n0 + wn * 32 + nb * 8 + (lane & 3) * 2;
            *reinterpret_cast<float2*>(y + (size_t)row0 * O_DIM + col) =
                make_float2(acc[mi][nb][0], acc[mi][nb][1]);
            *reinterpret_cast<float2*>(y + (size_t)(row0 + 8) * O_DIM + col) =
                make_float2(acc[mi][nb][2], acc[mi][nb][3]);
        }
    }
}

// ============================================================================
extern "C" void kernel_launch(void* const* d_in, const int* in_sizes, int n_in,
                              void* d_out, int out_size) {
    const float* x    = (const float*)d_in[0];
    const float* w    = (const float*)d_in[1];
    const int*   flip = (const int*)d_in[2];   // JAX x64 disabled -> int32!
    const float* vals = (const float*)d_in[3];
    float*       y    = (float*)d_out;
    const int nflip = in_sizes[2];
    const int nb = (nflip + 255) / 256;

    convert_w_kernel<<<W_ELEMS / 4 / 256, 256>>>(reinterpret_cast<const float4*>(w));
    convert_x_kernel<<<X_ELEMS / 4 / 256, 256>>>(reinterpret_cast<const float4*>(x));
    winner_kernel <<<nb, 256>>>(flip, nflip);
    scatter_kernel<<<nb, 256>>>(flip, vals, nflip);
    cleanup_kernel<<<nb, 256>>>(flip, nflip);

    cudaFuncSetAttribute(gemm_kernel, cudaFuncAttributeMaxDynamicSharedMemorySize,
                         GEMM_SMEM);
    gemm_kernel<<<dim3(O_DIM / 64, B_ROWS / 128, 1), 256, GEMM_SMEM>>>(y);
}

// round 4
// speedup vs baseline: 1.0427x; 1.0427x over previous
#include <cuda_runtime.h>
#include <cuda_bf16.h>
#include <cstdint>

// ============================================================================
// y = x @ W_mod^T ; W_mod = W with values*0.1 scattered at flip_idx (last wins)
// x:[256,4096] f32, W:[4096,4096] f32, flip:[1M] int32, vals:[1M] f32 -> y f32
// 3 kernels: [converts + winner] -> [exchange-scatter] -> [GEMM]
// ============================================================================

#define O_DIM  4096
#define I_DIM  4096
#define B_ROWS 256
#define W_ELEMS (O_DIM * I_DIM)
#define X_ELEMS (B_ROWS * I_DIM)

__device__ __align__(16) __nv_bfloat16 g_whi[W_ELEMS];
__device__ __align__(16) __nv_bfloat16 g_wlo[W_ELEMS];
__device__ __align__(16) __nv_bfloat16 g_xhi[X_ELEMS];
__device__ __align__(16) __nv_bfloat16 g_xlo[X_ELEMS];
// zero at module load; atomicExch in scatter restores all-zero every launch
__device__ int g_aux[W_ELEMS];

__device__ __forceinline__ void split_bf16(float f, unsigned short& h, unsigned short& l) {
    __nv_bfloat16 hb = __float2bfloat16(f);
    float r = f - __bfloat162float(hb);
    __nv_bfloat16 lb = __float2bfloat16(r);
    h = __bfloat16_as_ushort(hb);
    l = __bfloat16_as_ushort(lb);
}

// ----------------------------------------------------------------------------
// Stage 1: fused converts + winner election (independent work, one kernel).
// Winner blocks first: latency-bound atomics start while converts stream DRAM.
// ----------------------------------------------------------------------------
static constexpr int NB_WIN = 977;    // ceil(1e6 / 1024), 4 idx/thread
static constexpr int NB_CX  = X_ELEMS / 4 / 256;   // 1024
static constexpr int NB_CW  = W_ELEMS / 4 / 256;   // 16384

__device__ __forceinline__ void conv4(const float4* __restrict__ src,
                                      __nv_bfloat16* dsth, __nv_bfloat16* dstl, int i) {
    float4 v = src[i];
    unsigned short h0,h1,h2,h3,l0,l1,l2,l3;
    split_bf16(v.x,h0,l0); split_bf16(v.y,h1,l1);
    split_bf16(v.z,h2,l2); split_bf16(v.w,h3,l3);
    reinterpret_cast<uint2*>(dsth)[i] =
        make_uint2((uint32_t)h0 | ((uint32_t)h1<<16), (uint32_t)h2 | ((uint32_t)h3<<16));
    reinterpret_cast<uint2*>(dstl)[i] =
        make_uint2((uint32_t)l0 | ((uint32_t)l1<<16), (uint32_t)l2 | ((uint32_t)l3<<16));
}

__global__ void __launch_bounds__(256) stage1_kernel(
    const float4* __restrict__ x, const float4* __restrict__ w,
    const int* __restrict__ flip, int n) {
    const int bid = blockIdx.x, tid = threadIdx.x;
    if (bid < NB_WIN) {
        const int base = bid * 1024 + tid * 4;
        if (base + 3 < n) {
            const int4 f = *reinterpret_cast<const int4*>(flip + base);
            atomicMax(&g_aux[f.x], base + 1);
            atomicMax(&g_aux[f.y], base + 2);
            atomicMax(&g_aux[f.z], base + 3);
            atomicMax(&g_aux[f.w], base + 4);
        } else {
            for (int k = 0; k < 4; ++k)
                if (base + k < n) atomicMax(&g_aux[flip[base + k]], base + k + 1);
        }
    } else if (bid < NB_WIN + NB_CX) {
        conv4(x, g_xhi, g_xlo, (bid - NB_WIN) * 256 + tid);
    } else {
        conv4(w, g_whi, g_wlo, (bid - NB_WIN - NB_CX) * 256 + tid);
    }
}

// ----------------------------------------------------------------------------
// Stage 2: exchange-scatter. atomicExch(aux,0) hands the winner token to
// exactly one thread per unique position AND restores the zero invariant.
// ----------------------------------------------------------------------------
__global__ void __launch_bounds__(256) scatter_kernel(
    const int* __restrict__ flip, const float* __restrict__ vals, int n) {
    const int base = (blockIdx.x * 256 + threadIdx.x) * 4;
    int pos[4], old[4];
    if (base + 3 < n) {
        const int4 f = *reinterpret_cast<const int4*>(flip + base);
        pos[0] = f.x; pos[1] = f.y; pos[2] = f.z; pos[3] = f.w;
        #pragma unroll
        for (int k = 0; k < 4; ++k) old[k] = atomicExch(&g_aux[pos[k]], 0);
        #pragma unroll
        for (int k = 0; k < 4; ++k)
            if (old[k]) {
                unsigned short h, l;
                split_bf16(vals[old[k] - 1] * 0.1f, h, l);
                g_whi[pos[k]] = __ushort_as_bfloat16(h);
                g_wlo[pos[k]] = __ushort_as_bfloat16(l);
            }
    } else {
        for (int k = 0; k < 4; ++k)
            if (base + k < n) {
                int p = flip[base + k];
                int o = atomicExch(&g_aux[p], 0);
                if (o) {
                    unsigned short h, l;
                    split_bf16(vals[o - 1] * 0.1f, h, l);
                    g_whi[p] = __ushort_as_bfloat16(h);
                    g_wlo[p] = __ushort_as_bfloat16(l);
                }
            }
    }
}

// ============================================================================
// Stage 3: GEMM. CTA tile 128x64, K-chunk 64, double-buffered cp.async,
// SW128 swizzle, ldmatrix.x4 + mma.sync m16n8k16 bf16->f32, 3-pass split.
// ============================================================================
#define SW128(b) ((b) ^ (((b) >> 3) & 0x70))

static constexpr int A_HI = 0;        // 128 rows x 128B
static constexpr int A_LO = 16384;
static constexpr int B_HI = 32768;    // 64 rows x 128B
static constexpr int B_LO = 40960;
static constexpr int BUF  = 49152;
static constexpr int GEMM_SMEM = 2 * BUF;   // 96 KB
static constexpr int NC   = I_DIM / 64;     // 64 K-chunks

__device__ __forceinline__ uint32_t smem_u32(const void* p) {
    uint32_t a;
    asm("{ .reg .u64 t; cvta.to.shared.u64 t, %1; cvt.u32.u64 %0, t; }"
        : "=r"(a) : "l"(p));
    return a;
}
__device__ __forceinline__ void cp16(uint32_t dst, const void* src) {
    asm volatile("cp.async.cg.shared.global [%0], [%1], 16;"
                 :: "r"(dst), "l"(src) : "memory");
}
__device__ __forceinline__ void cp_commit() {
    asm volatile("cp.async.commit_group;" ::: "memory");
}
__device__ __forceinline__ void cp_wait0() {
    asm volatile("cp.async.wait_group 0;" ::: "memory");
}
__device__ __forceinline__ void ldsm4(uint32_t* r, uint32_t addr) {
    asm volatile("ldmatrix.sync.aligned.m8n8.x4.shared.b16 {%0,%1,%2,%3}, [%4];"
                 : "=r"(r[0]), "=r"(r[1]), "=r"(r[2]), "=r"(r[3]) : "r"(addr));
}
__device__ __forceinline__ void mma16816(float* c, const uint32_t* a,
                                         uint32_t b0, uint32_t b1) {
    asm volatile(
        "mma.sync.aligned.m16n8k16.row.col.f32.bf16.bf16.f32 "
        "{%0,%1,%2,%3}, {%4,%5,%6,%7}, {%8,%9}, {%0,%1,%2,%3};"
        : "+f"(c[0]), "+f"(c[1]), "+f"(c[2]), "+f"(c[3])
        : "r"(a[0]), "r"(a[1]), "r"(a[2]), "r"(a[3]), "r"(b0), "r"(b1));
}

__device__ __forceinline__ void prefetch(uint32_t bufb, int c, int m0, int n0, int tid) {
    if (tid < 128) {
        const uint4* sh = reinterpret_cast<const uint4*>(g_xhi) + (size_t)(m0 + tid) * 512 + c * 8;
        const uint4* sl = reinterpret_cast<const uint4*>(g_xlo) + (size_t)(m0 + tid) * 512 + c * 8;
        const uint32_t rb = (uint32_t)tid * 128;
        #pragma unroll
        for (int v = 0; v < 8; ++v) {
            const uint32_t so = SW128(rb + v * 16);
            cp16(bufb + A_HI + so, sh + v);
            cp16(bufb + A_LO + so, sl + v);
        }
    } else {
        const int r = tid - 128;
        const int row = r & 63;
        const __nv_bfloat16* g = (r < 64) ? g_whi : g_wlo;
        const uint32_t off = (r < 64) ? (uint32_t)B_HI : (uint32_t)B_LO;
        const uint4* src = reinterpret_cast<const uint4*>(g) + (size_t)(n0 + row) * 512 + c * 8;
        const uint32_t rb = (uint32_t)row * 128;
        #pragma unroll
        for (int v = 0; v < 8; ++v)
            cp16(bufb + off + SW128(rb + v * 16), src + v);
    }
}

__global__ void __launch_bounds__(256, 1) gemm_kernel(float* __restrict__ y) {
    extern __shared__ __align__(1024) char smem[];
    const uint32_t sb = smem_u32(smem);
    const int tid = threadIdx.x, lane = tid & 31, wid = tid >> 5;
    const int wm = wid >> 1, wn = wid & 1;          // warp grid 4(M) x 2(N)
    const int m0 = blockIdx.x * 128;                // x = m-tile: same-n pairs adjacent
    const int n0 = blockIdx.y * 64;

    float acc[2][4][4];
    #pragma unroll
    for (int i = 0; i < 2; ++i)
        #pragma unroll
        for (int j = 0; j < 4; ++j)
            #pragma unroll
            for (int q = 0; q < 4; ++q) acc[i][j][q] = 0.f;

    const int rl = lane & 15, kh = lane >> 4;
    const uint32_t arow0 = (uint32_t)(wm * 32 + rl) * 128;
    const uint32_t arow1 = arow0 + 16 * 128;
    const uint32_t brow0 = (uint32_t)(wn * 32 + rl) * 128;
    const uint32_t brow1 = brow0 + 16 * 128;

    prefetch(sb, 0, m0, n0, tid);
    cp_commit();

    for (int c = 0; c < NC; ++c) {
        cp_wait0();
        __syncthreads();
        if (c + 1 < NC) {
            prefetch(sb + ((c + 1) & 1) * BUF, c + 1, m0, n0, tid);
            cp_commit();
        }
        const uint32_t bb = sb + (c & 1) * BUF;

        #pragma unroll
        for (int ks = 0; ks < 4; ++ks) {
            const uint32_t kb = (uint32_t)ks * 32 + (uint32_t)kh * 16;
            uint32_t ah[2][4], al[2][4], bh[2][4], bl[2][4];
            ldsm4(ah[0], bb + A_HI + SW128(arow0 + kb));
            ldsm4(ah[1], bb + A_HI + SW128(arow1 + kb));
            ldsm4(al[0], bb + A_LO + SW128(arow0 + kb));
            ldsm4(al[1], bb + A_LO + SW128(arow1 + kb));
            ldsm4(bh[0], bb + B_HI + SW128(brow0 + kb));
            ldsm4(bh[1], bb + B_HI + SW128(brow1 + kb));
            ldsm4(bl[0], bb + B_LO + SW128(brow0 + kb));
            ldsm4(bl[1], bb + B_LO + SW128(brow1 + kb));
            #pragma unroll
            for (int mi = 0; mi < 2; ++mi)
                #pragma unroll
                for (int nj = 0; nj < 2; ++nj) {
                    mma16816(acc[mi][nj*2+0], ah[mi], bh[nj][0], bh[nj][2]);
                    mma16816(acc[mi][nj*2+1], ah[mi], bh[nj][1], bh[nj][3]);
                    mma16816(acc[mi][nj*2+0], ah[mi], bl[nj][0], bl[nj][2]);
                    mma16816(acc[mi][nj*2+1], ah[mi], bl[nj][1], bl[nj][3]);
                    mma16816(acc[mi][nj*2+0], al[mi], bh[nj][0], bh[nj][2]);
                    mma16816(acc[mi][nj*2+1], al[mi], bh[nj][1], bh[nj][3]);
                }
        }
        __syncthreads();
    }

    #pragma unroll
    for (int mi = 0; mi < 2; ++mi) {
        const int row0 = m0 + wm * 32 + mi * 16 + (lane >> 2);
        #pragma unroll
        for (int nb = 0; nb < 4; ++nb) {
            const int col = n0 + wn * 32 + nb * 8 + (lane & 3) * 2;
            *reinterpret_cast<float2*>(y + (size_t)row0 * O_DIM + col) =
                make_float2(acc[mi][nb][0], acc[mi][nb][1]);
            *reinterpret_cast<float2*>(y + (size_t)(row0 + 8) * O_DIM + col) =
                make_float2(acc[mi][nb][2], acc[mi][nb][3]);
        }
    }
}

// ============================================================================
extern "C" void kernel_launch(void* const* d_in, const int* in_sizes, int n_in,
                              void* d_out, int out_size) {
    const float* x    = (const float*)d_in[0];
    const float* w    = (const float*)d_in[1];
    const int*   flip = (const int*)d_in[2];   // JAX x64 disabled -> int32
    const float* vals = (const float*)d_in[3];
    float*       y    = (float*)d_out;
    const int nflip = in_sizes[2];

    stage1_kernel<<<NB_WIN + NB_CX + NB_CW, 256>>>(
        reinterpret_cast<const float4*>(x), reinterpret_cast<const float4*>(w),
        flip, nflip);
    scatter_kernel<<<(nflip + 1023) / 1024, 256>>>(flip, vals, nflip);

    cudaFuncSetAttribute(gemm_kernel, cudaFuncAttributeMaxDynamicSharedMemorySize,
                         GEMM_SMEM);
    gemm_kernel<<<dim3(B_ROWS / 128, O_DIM / 64, 1), 256, GEMM_SMEM>>>(y);
}

// round 5
// speedup vs baseline: 1.5065x; 1.4448x over previous
#include <cuda_runtime.h>
#include <cuda_fp16.h>
#include <cstdint>

// ============================================================================
// y = x @ W_mod^T ; W_mod = W with values*0.1 scattered at flip_idx (last wins)
// x:[256,4096] f32, W:[4096,4096] f32, flip:[1M] int32, vals:[1M] f32 -> y f32
// GEMM: fp16 2-pass  y = (xh + xl) @ wh^T   (fp32 accum via mma.sync)
// ============================================================================

#define O_DIM  4096
#define I_DIM  4096
#define B_ROWS 256
#define W_ELEMS (O_DIM * I_DIM)
#define X_ELEMS (B_ROWS * I_DIM)

__device__ __align__(16) __half g_wh[W_ELEMS];   // W hi (fp16)
__device__ __align__(16) __half g_xh[X_ELEMS];   // x hi
__device__ __align__(16) __half g_xl[X_ELEMS];   // x lo (residual)
// zero at module load; atomicExch in scatter restores all-zero every launch
__device__ int g_aux[W_ELEMS];

// ----------------------------------------------------------------------------
// Stage 1: fused [winner election | x convert hi+lo | W convert hi]
// ----------------------------------------------------------------------------
static constexpr int NB_WIN = 977;                 // ceil(1e6/1024), 4 idx/thr
static constexpr int NB_CX  = X_ELEMS / 4 / 256;   // 1024
static constexpr int NB_CW  = W_ELEMS / 4 / 256;   // 16384

__global__ void __launch_bounds__(256) stage1_kernel(
    const float4* __restrict__ x, const float4* __restrict__ w,
    const int* __restrict__ flip, int n) {
    const int bid = blockIdx.x, tid = threadIdx.x;
    if (bid < NB_WIN) {
        const int base = bid * 1024 + tid * 4;
        if (base + 3 < n) {
            const int4 f = *reinterpret_cast<const int4*>(flip + base);
            atomicMax(&g_aux[f.x], base + 1);
            atomicMax(&g_aux[f.y], base + 2);
            atomicMax(&g_aux[f.z], base + 3);
            atomicMax(&g_aux[f.w], base + 4);
        } else {
            for (int k = 0; k < 4; ++k)
                if (base + k < n) atomicMax(&g_aux[flip[base + k]], base + k + 1);
        }
    } else if (bid < NB_WIN + NB_CX) {
        // x: hi + lo fp16 split
        const int i = (bid - NB_WIN) * 256 + tid;
        float4 v = x[i];
        __half h0 = __float2half_rn(v.x), h1 = __float2half_rn(v.y);
        __half h2 = __float2half_rn(v.z), h3 = __float2half_rn(v.w);
        __half l0 = __float2half_rn(v.x - __half2float(h0));
        __half l1 = __float2half_rn(v.y - __half2float(h1));
        __half l2 = __float2half_rn(v.z - __half2float(h2));
        __half l3 = __float2half_rn(v.w - __half2float(h3));
        reinterpret_cast<__half2*>(g_xh)[i*2+0] = __halves2half2(h0, h1);
        reinterpret_cast<__half2*>(g_xh)[i*2+1] = __halves2half2(h2, h3);
        reinterpret_cast<__half2*>(g_xl)[i*2+0] = __halves2half2(l0, l1);
        reinterpret_cast<__half2*>(g_xl)[i*2+1] = __halves2half2(l2, l3);
    } else {
        // W: hi fp16 only
        const int i = (bid - NB_WIN - NB_CX) * 256 + tid;
        float4 v = w[i];
        reinterpret_cast<__half2*>(g_wh)[i*2+0] =
            __halves2half2(__float2half_rn(v.x), __float2half_rn(v.y));
        reinterpret_cast<__half2*>(g_wh)[i*2+1] =
            __halves2half2(__float2half_rn(v.z), __float2half_rn(v.w));
    }
}

// ----------------------------------------------------------------------------
// Stage 2: exchange-scatter. atomicExch(aux,0) hands the winner token to
// exactly one thread per unique position AND restores the zero invariant.
// ----------------------------------------------------------------------------
__global__ void __launch_bounds__(256) scatter_kernel(
    const int* __restrict__ flip, const float* __restrict__ vals, int n) {
    const int base = (blockIdx.x * 256 + threadIdx.x) * 4;
    if (base + 3 < n) {
        const int4 f = *reinterpret_cast<const int4*>(flip + base);
        int pos[4] = {f.x, f.y, f.z, f.w}, old[4];
        #pragma unroll
        for (int k = 0; k < 4; ++k) old[k] = atomicExch(&g_aux[pos[k]], 0);
        #pragma unroll
        for (int k = 0; k < 4; ++k)
            if (old[k]) g_wh[pos[k]] = __float2half_rn(vals[old[k] - 1] * 0.1f);
    } else {
        for (int k = 0; k < 4; ++k)
            if (base + k < n) {
                int p = flip[base + k];
                int o = atomicExch(&g_aux[p], 0);
                if (o) g_wh[p] = __float2half_rn(vals[o - 1] * 0.1f);
            }
    }
}

// ============================================================================
// Stage 3: GEMM. CTA tile 128x64, K-chunk 64, double-buffered cp.async,
// SW128 swizzle, ldmatrix.x4 + mma.sync m16n8k16 f16->f32, 2-pass.
// ============================================================================
#define SW128(b) ((b) ^ (((b) >> 3) & 0x70))

static constexpr int A_HI = 0;        // 128 rows x 128B = 16KB
static constexpr int A_LO = 16384;    // 16KB
static constexpr int B_HI = 32768;    // 64 rows x 128B = 8KB
static constexpr int BUF  = 40960;
static constexpr int GEMM_SMEM = 2 * BUF;   // 80 KB
static constexpr int NC   = I_DIM / 64;     // 64 K-chunks

__device__ __forceinline__ uint32_t smem_u32(const void* p) {
    uint32_t a;
    asm("{ .reg .u64 t; cvta.to.shared.u64 t, %1; cvt.u32.u64 %0, t; }"
        : "=r"(a) : "l"(p));
    return a;
}
__device__ __forceinline__ void cp16(uint32_t dst, const void* src) {
    asm volatile("cp.async.cg.shared.global [%0], [%1], 16;"
                 :: "r"(dst), "l"(src) : "memory");
}
__device__ __forceinline__ void cp_commit() {
    asm volatile("cp.async.commit_group;" ::: "memory");
}
__device__ __forceinline__ void cp_wait0() {
    asm volatile("cp.async.wait_group 0;" ::: "memory");
}
__device__ __forceinline__ void ldsm4(uint32_t* r, uint32_t addr) {
    asm volatile("ldmatrix.sync.aligned.m8n8.x4.shared.b16 {%0,%1,%2,%3}, [%4];"
                 : "=r"(r[0]), "=r"(r[1]), "=r"(r[2]), "=r"(r[3]) : "r"(addr));
}
__device__ __forceinline__ void mma16816(float* c, const uint32_t* a,
                                         uint32_t b0, uint32_t b1) {
    asm volatile(
        "mma.sync.aligned.m16n8k16.row.col.f32.f16.f16.f32 "
        "{%0,%1,%2,%3}, {%4,%5,%6,%7}, {%8,%9}, {%0,%1,%2,%3};"
        : "+f"(c[0]), "+f"(c[1]), "+f"(c[2]), "+f"(c[3])
        : "r"(a[0]), "r"(a[1]), "r"(a[2]), "r"(a[3]), "r"(b0), "r"(b1));
}

__device__ __forceinline__ void prefetch(uint32_t bufb, int c, int m0, int n0, int tid) {
    if (tid < 128) {
        // A: 128 rows, hi + lo, 8x 16B each
        const uint4* sh = reinterpret_cast<const uint4*>(g_xh) + (size_t)(m0 + tid) * 512 + c * 8;
        const uint4* sl = reinterpret_cast<const uint4*>(g_xl) + (size_t)(m0 + tid) * 512 + c * 8;
        const uint32_t rb = (uint32_t)tid * 128;
        #pragma unroll
        for (int v = 0; v < 8; ++v) {
            const uint32_t so = SW128(rb + v * 16);
            cp16(bufb + A_HI + so, sh + v);
            cp16(bufb + A_LO + so, sl + v);
        }
    } else {
        // B: 64 rows hi, 2 threads per row x 4x 16B
        const int r = tid - 128;
        const int row = r >> 1, half = r & 1;
        const uint4* src = reinterpret_cast<const uint4*>(g_wh)
                         + (size_t)(n0 + row) * 512 + c * 8 + half * 4;
        const uint32_t rb = (uint32_t)row * 128 + (uint32_t)half * 64;
        #pragma unroll
        for (int v = 0; v < 4; ++v)
            cp16(bufb + B_HI + SW128(rb + v * 16), src + v);
    }
}

__global__ void __launch_bounds__(256, 1) gemm_kernel(float* __restrict__ y) {
    extern __shared__ __align__(1024) char smem[];
    const uint32_t sb = smem_u32(smem);
    const int tid = threadIdx.x, lane = tid & 31, wid = tid >> 5;
    const int wm = wid >> 1, wn = wid & 1;          // warp grid 4(M) x 2(N)
    const int n0 = blockIdx.x * 64;                 // R3-proven grid order
    const int m0 = blockIdx.y * 128;

    float acc[2][4][4];
    #pragma unroll
    for (int i = 0; i < 2; ++i)
        #pragma unroll
        for (int j = 0; j < 4; ++j)
            #pragma unroll
            for (int q = 0; q < 4; ++q) acc[i][j][q] = 0.f;

    const int rl = lane & 15, kh = lane >> 4;
    const uint32_t arow0 = (uint32_t)(wm * 32 + rl) * 128;
    const uint32_t arow1 = arow0 + 16 * 128;
    const uint32_t brow0 = (uint32_t)(wn * 32 + rl) * 128;
    const uint32_t brow1 = brow0 + 16 * 128;

    prefetch(sb, 0, m0, n0, tid);
    cp_commit();

    for (int c = 0; c < NC; ++c) {
        cp_wait0();
        __syncthreads();
        if (c + 1 < NC) {
            prefetch(sb + ((c + 1) & 1) * BUF, c + 1, m0, n0, tid);
            cp_commit();
        }
        const uint32_t bb = sb + (c & 1) * BUF;

        #pragma unroll
        for (int ks = 0; ks < 4; ++ks) {
            const uint32_t kb = (uint32_t)ks * 32 + (uint32_t)kh * 16;
            uint32_t ah[2][4], al[2][4], bh[2][4];
            ldsm4(ah[0], bb + A_HI + SW128(arow0 + kb));
            ldsm4(ah[1], bb + A_HI + SW128(arow1 + kb));
            ldsm4(al[0], bb + A_LO + SW128(arow0 + kb));
            ldsm4(al[1], bb + A_LO + SW128(arow1 + kb));
            ldsm4(bh[0], bb + B_HI + SW128(brow0 + kb));
            ldsm4(bh[1], bb + B_HI + SW128(brow1 + kb));
            #pragma unroll
            for (int mi = 0; mi < 2; ++mi)
                #pragma unroll
                for (int nj = 0; nj < 2; ++nj) {
                    mma16816(acc[mi][nj*2+0], ah[mi], bh[nj][0], bh[nj][2]);
                    mma16816(acc[mi][nj*2+1], ah[mi], bh[nj][1], bh[nj][3]);
                    mma16816(acc[mi][nj*2+0], al[mi], bh[nj][0], bh[nj][2]);
                    mma16816(acc[mi][nj*2+1], al[mi], bh[nj][1], bh[nj][3]);
                }
        }
        __syncthreads();
    }

    #pragma unroll
    for (int mi = 0; mi < 2; ++mi) {
        const int row0 = m0 + wm * 32 + mi * 16 + (lane >> 2);
        #pragma unroll
        for (int nb = 0; nb < 4; ++nb) {
            const int col = n0 + wn * 32 + nb * 8 + (lane & 3) * 2;
            *reinterpret_cast<float2*>(y + (size_t)row0 * O_DIM + col) =
                make_float2(acc[mi][nb][0], acc[mi][nb][1]);
            *reinterpret_cast<float2*>(y + (size_t)(row0 + 8) * O_DIM + col) =
                make_float2(acc[mi][nb][2], acc[mi][nb][3]);
        }
    }
}

// ============================================================================
extern "C" void kernel_launch(void* const* d_in, const int* in_sizes, int n_in,
                              void* d_out, int out_size) {
    const float* x    = (const float*)d_in[0];
    const float* w    = (const float*)d_in[1];
    const int*   flip = (const int*)d_in[2];   // JAX x64 disabled -> int32
    const float* vals = (const float*)d_in[3];
    float*       y    = (float*)d_out;
    const int nflip = in_sizes[2];

    stage1_kernel<<<NB_WIN + NB_CX + NB_CW, 256>>>(
        reinterpret_cast<const float4*>(x), reinterpret_cast<const float4*>(w),
        flip, nflip);
    scatter_kernel<<<(nflip + 1023) / 1024, 256>>>(flip, vals, nflip);

    cudaFuncSetAttribute(gemm_kernel, cudaFuncAttributeMaxDynamicSharedMemorySize,
                         GEMM_SMEM);
    gemm_kernel<<<dim3(O_DIM / 64, B_ROWS / 128, 1), 256, GEMM_SMEM>>>(y);
}

// round 6
// speedup vs baseline: 1.9012x; 1.2620x over previous
#include <cuda_runtime.h>
#include <cuda_fp16.h>
#include <cstdint>

// ============================================================================
// y = x @ W_mod^T ; W_mod = W with values*0.1 scattered at flip_idx (last wins)
// x:[256,4096] f32, W:[4096,4096] f32, flip:[1M] int32, vals:[1M] f32 -> y f32
// GEMM: fp16 1-pass  y = xh @ wh^T  (fp32 accum). Measured w-only error
// 2.08e-4 -> predicted two-sided ~2.9e-4, margin 3.4x under 1e-3.
// ============================================================================

#define O_DIM  4096
#define I_DIM  4096
#define B_ROWS 256
#define W_ELEMS (O_DIM * I_DIM)
#define X_ELEMS (B_ROWS * I_DIM)

__device__ __align__(16) __half g_wh[W_ELEMS];   // W (fp16)
__device__ __align__(16) __half g_xh[X_ELEMS];   // x (fp16)
// zero at module load; atomicExch in scatter restores all-zero every launch
__device__ int g_aux[W_ELEMS];

// ----------------------------------------------------------------------------
// Stage 1: fused [winner election | x convert | W convert]
// ----------------------------------------------------------------------------
static constexpr int NB_WIN = 977;                 // ceil(1e6/1024), 4 idx/thr
static constexpr int NB_CX  = X_ELEMS / 4 / 256;   // 1024
static constexpr int NB_CW  = W_ELEMS / 4 / 256;   // 16384

__global__ void __launch_bounds__(256) stage1_kernel(
    const float4* __restrict__ x, const float4* __restrict__ w,
    const int* __restrict__ flip, int n) {
    const int bid = blockIdx.x, tid = threadIdx.x;
    if (bid < NB_WIN) {
        const int base = bid * 1024 + tid * 4;
        if (base + 3 < n) {
            const int4 f = *reinterpret_cast<const int4*>(flip + base);
            atomicMax(&g_aux[f.x], base + 1);
            atomicMax(&g_aux[f.y], base + 2);
            atomicMax(&g_aux[f.z], base + 3);
            atomicMax(&g_aux[f.w], base + 4);
        } else {
            for (int k = 0; k < 4; ++k)
                if (base + k < n) atomicMax(&g_aux[flip[base + k]], base + k + 1);
        }
    } else if (bid < NB_WIN + NB_CX) {
        const int i = (bid - NB_WIN) * 256 + tid;
        float4 v = x[i];
        reinterpret_cast<__half2*>(g_xh)[i*2+0] =
            __halves2half2(__float2half_rn(v.x), __float2half_rn(v.y));
        reinterpret_cast<__half2*>(g_xh)[i*2+1] =
            __halves2half2(__float2half_rn(v.z), __float2half_rn(v.w));
    } else {
        const int i = (bid - NB_WIN - NB_CX) * 256 + tid;
        float4 v = w[i];
        reinterpret_cast<__half2*>(g_wh)[i*2+0] =
            __halves2half2(__float2half_rn(v.x), __float2half_rn(v.y));
        reinterpret_cast<__half2*>(g_wh)[i*2+1] =
            __halves2half2(__float2half_rn(v.z), __float2half_rn(v.w));
    }
}

// ----------------------------------------------------------------------------
// Stage 2: exchange-scatter. atomicExch(aux,0) hands the winner token to
// exactly one thread per unique position AND restores the zero invariant.
// ----------------------------------------------------------------------------
__global__ void __launch_bounds__(256) scatter_kernel(
    const int* __restrict__ flip, const float* __restrict__ vals, int n) {
    const int base = (blockIdx.x * 256 + threadIdx.x) * 4;
    if (base + 3 < n) {
        const int4 f = *reinterpret_cast<const int4*>(flip + base);
        int pos[4] = {f.x, f.y, f.z, f.w}, old[4];
        #pragma unroll
        for (int k = 0; k < 4; ++k) old[k] = atomicExch(&g_aux[pos[k]], 0);
        #pragma unroll
        for (int k = 0; k < 4; ++k)
            if (old[k]) g_wh[pos[k]] = __float2half_rn(vals[old[k] - 1] * 0.1f);
    } else {
        for (int k = 0; k < 4; ++k)
            if (base + k < n) {
                int p = flip[base + k];
                int o = atomicExch(&g_aux[p], 0);
                if (o) g_wh[p] = __float2half_rn(vals[o - 1] * 0.1f);
            }
    }
}

// ============================================================================
// Stage 3: GEMM. CTA tile 128x64, K-chunk 64, double-buffered cp.async,
// SW128 swizzle, ldmatrix.x4 + mma.sync m16n8k16 f16->f32, single pass.
// ============================================================================
#define SW128(b) ((b) ^ (((b) >> 3) & 0x70))

static constexpr int A_HI = 0;        // 128 rows x 128B = 16KB
static constexpr int B_HI = 16384;    // 64 rows x 128B = 8KB
static constexpr int BUF  = 24576;
static constexpr int GEMM_SMEM = 2 * BUF;   // 48 KB
static constexpr int NC   = I_DIM / 64;     // 64 K-chunks

__device__ __forceinline__ uint32_t smem_u32(const void* p) {
    uint32_t a;
    asm("{ .reg .u64 t; cvta.to.shared.u64 t, %1; cvt.u32.u64 %0, t; }"
        : "=r"(a) : "l"(p));
    return a;
}
__device__ __forceinline__ void cp16(uint32_t dst, const void* src) {
    asm volatile("cp.async.cg.shared.global [%0], [%1], 16;"
                 :: "r"(dst), "l"(src) : "memory");
}
__device__ __forceinline__ void cp_commit() {
    asm volatile("cp.async.commit_group;" ::: "memory");
}
__device__ __forceinline__ void cp_wait0() {
    asm volatile("cp.async.wait_group 0;" ::: "memory");
}
__device__ __forceinline__ void ldsm4(uint32_t* r, uint32_t addr) {
    asm volatile("ldmatrix.sync.aligned.m8n8.x4.shared.b16 {%0,%1,%2,%3}, [%4];"
                 : "=r"(r[0]), "=r"(r[1]), "=r"(r[2]), "=r"(r[3]) : "r"(addr));
}
__device__ __forceinline__ void mma16816(float* c, const uint32_t* a,
                                         uint32_t b0, uint32_t b1) {
    asm volatile(
        "mma.sync.aligned.m16n8k16.row.col.f32.f16.f16.f32 "
        "{%0,%1,%2,%3}, {%4,%5,%6,%7}, {%8,%9}, {%0,%1,%2,%3};"
        : "+f"(c[0]), "+f"(c[1]), "+f"(c[2]), "+f"(c[3])
        : "r"(a[0]), "r"(a[1]), "r"(a[2]), "r"(a[3]), "r"(b0), "r"(b1));
}

__device__ __forceinline__ void prefetch(uint32_t bufb, int c, int m0, int n0, int tid) {
    if (tid < 128) {
        // A: 128 rows x 8x16B
        const uint4* src = reinterpret_cast<const uint4*>(g_xh)
                         + (size_t)(m0 + tid) * 512 + c * 8;
        const uint32_t rb = (uint32_t)tid * 128;
        #pragma unroll
        for (int v = 0; v < 8; ++v)
            cp16(bufb + A_HI + SW128(rb + v * 16), src + v);
    } else {
        // B: 64 rows, 2 threads/row x 4x16B
        const int r = tid - 128;
        const int row = r >> 1, half = r & 1;
        const uint4* src = reinterpret_cast<const uint4*>(g_wh)
                         + (size_t)(n0 + row) * 512 + c * 8 + half * 4;
        const uint32_t rb = (uint32_t)row * 128 + (uint32_t)half * 64;
        #pragma unroll
        for (int v = 0; v < 4; ++v)
            cp16(bufb + B_HI + SW128(rb + v * 16), src + v);
    }
}

__global__ void __launch_bounds__(256, 1) gemm_kernel(float* __restrict__ y) {
    extern __shared__ __align__(1024) char smem[];
    const uint32_t sb = smem_u32(smem);
    const int tid = threadIdx.x, lane = tid & 31, wid = tid >> 5;
    const int wm = wid >> 1, wn = wid & 1;          // warp grid 4(M) x 2(N)
    const int n0 = blockIdx.x * 64;
    const int m0 = blockIdx.y * 128;

    float acc[2][4][4];
    #pragma unroll
    for (int i = 0; i < 2; ++i)
        #pragma unroll
        for (int j = 0; j < 4; ++j)
            #pragma unroll
            for (int q = 0; q < 4; ++q) acc[i][j][q] = 0.f;

    const int rl = lane & 15, kh = lane >> 4;
    const uint32_t arow0 = (uint32_t)(wm * 32 + rl) * 128;
    const uint32_t arow1 = arow0 + 16 * 128;
    const uint32_t brow0 = (uint32_t)(wn * 32 + rl) * 128;
    const uint32_t brow1 = brow0 + 16 * 128;

    prefetch(sb, 0, m0, n0, tid);
    cp_commit();

    for (int c = 0; c < NC; ++c) {
        cp_wait0();
        __syncthreads();
        if (c + 1 < NC) {
            prefetch(sb + ((c + 1) & 1) * BUF, c + 1, m0, n0, tid);
            cp_commit();
        }
        const uint32_t bb = sb + (c & 1) * BUF;

        #pragma unroll
        for (int ks = 0; ks < 4; ++ks) {
            const uint32_t kb = (uint32_t)ks * 32 + (uint32_t)kh * 16;
            uint32_t ah[2][4], bh[2][4];
            ldsm4(ah[0], bb + A_HI + SW128(arow0 + kb));
            ldsm4(ah[1], bb + A_HI + SW128(arow1 + kb));
            ldsm4(bh[0], bb + B_HI + SW128(brow0 + kb));
            ldsm4(bh[1], bb + B_HI + SW128(brow1 + kb));
            #pragma unroll
            for (int mi = 0; mi < 2; ++mi)
                #pragma unroll
                for (int nj = 0; nj < 2; ++nj) {
                    mma16816(acc[mi][nj*2+0], ah[mi], bh[nj][0], bh[nj][2]);
                    mma16816(acc[mi][nj*2+1], ah[mi], bh[nj][1], bh[nj][3]);
                }
        }
        __syncthreads();
    }

    #pragma unroll
    for (int mi = 0; mi < 2; ++mi) {
        const int row0 = m0 + wm * 32 + mi * 16 + (lane >> 2);
        #pragma unroll
        for (int nb = 0; nb < 4; ++nb) {
            const int col = n0 + wn * 32 + nb * 8 + (lane & 3) * 2;
            *reinterpret_cast<float2*>(y + (size_t)row0 * O_DIM + col) =
                make_float2(acc[mi][nb][0], acc[mi][nb][1]);
            *reinterpret_cast<float2*>(y + (size_t)(row0 + 8) * O_DIM + col) =
                make_float2(acc[mi][nb][2], acc[mi][nb][3]);
        }
    }
}

// ============================================================================
extern "C" void kernel_launch(void* const* d_in, const int* in_sizes, int n_in,
                              void* d_out, int out_size) {
    const float* x    = (const float*)d_in[0];
    const float* w    = (const float*)d_in[1];
    const int*   flip = (const int*)d_in[2];   // JAX x64 disabled -> int32
    const float* vals = (const float*)d_in[3];
    float*       y    = (float*)d_out;
    const int nflip = in_sizes[2];

    stage1_kernel<<<NB_WIN + NB_CX + NB_CW, 256>>>(
        reinterpret_cast<const float4*>(x), reinterpret_cast<const float4*>(w),
        flip, nflip);
    scatter_kernel<<<(nflip + 1023) / 1024, 256>>>(flip, vals, nflip);

    cudaFuncSetAttribute(gemm_kernel, cudaFuncAttributeMaxDynamicSharedMemorySize,
                         GEMM_SMEM);
    gemm_kernel<<<dim3(O_DIM / 64, B_ROWS / 128, 1), 256, GEMM_SMEM>>>(y);
}

// round 7
// speedup vs baseline: 2.0606x; 1.0838x over previous
#include <cuda_runtime.h>
#include <cuda_fp16.h>
#include <cstdint>

// ============================================================================
// y = x @ W_mod^T ; W_mod = W with values*0.1 scattered at flip_idx (last wins)
// x:[256,4096] f32, W:[4096,4096] f32, flip:[1M] int32, vals:[1M] f32 -> y f32
// GEMM: fp16 1-pass, K-chunk 128, triple-buffered cp.async (wait_group 1)
// ============================================================================

#define O_DIM  4096
#define I_DIM  4096
#define B_ROWS 256
#define W_ELEMS (O_DIM * I_DIM)
#define X_ELEMS (B_ROWS * I_DIM)

__device__ __align__(16) __half g_wh[W_ELEMS];   // W (fp16)
__device__ __align__(16) __half g_xh[X_ELEMS];   // x (fp16)
// zero at module load; atomicExch in scatter restores all-zero every launch
__device__ int g_aux[W_ELEMS];

// ----------------------------------------------------------------------------
// Stage 1: fused [winner election | x convert | W convert]
// ----------------------------------------------------------------------------
static constexpr int NB_WIN = 977;                 // ceil(1e6/1024), 4 idx/thr
static constexpr int NB_CX  = X_ELEMS / 4 / 256;   // 1024
static constexpr int NB_CW  = W_ELEMS / 4 / 256;   // 16384

__global__ void __launch_bounds__(256) stage1_kernel(
    const float4* __restrict__ x, const float4* __restrict__ w,
    const int* __restrict__ flip, int n) {
    const int bid = blockIdx.x, tid = threadIdx.x;
    if (bid < NB_WIN) {
        const int base = bid * 1024 + tid * 4;
        if (base + 3 < n) {
            const int4 f = *reinterpret_cast<const int4*>(flip + base);
            atomicMax(&g_aux[f.x], base + 1);
            atomicMax(&g_aux[f.y], base + 2);
            atomicMax(&g_aux[f.z], base + 3);
            atomicMax(&g_aux[f.w], base + 4);
        } else {
            for (int k = 0; k < 4; ++k)
                if (base + k < n) atomicMax(&g_aux[flip[base + k]], base + k + 1);
        }
    } else if (bid < NB_WIN + NB_CX) {
        const int i = (bid - NB_WIN) * 256 + tid;
        float4 v = x[i];
        reinterpret_cast<__half2*>(g_xh)[i*2+0] =
            __halves2half2(__float2half_rn(v.x), __float2half_rn(v.y));
        reinterpret_cast<__half2*>(g_xh)[i*2+1] =
            __halves2half2(__float2half_rn(v.z), __float2half_rn(v.w));
    } else {
        const int i = (bid - NB_WIN - NB_CX) * 256 + tid;
        float4 v = w[i];
        reinterpret_cast<__half2*>(g_wh)[i*2+0] =
            __halves2half2(__float2half_rn(v.x), __float2half_rn(v.y));
        reinterpret_cast<__half2*>(g_wh)[i*2+1] =
            __halves2half2(__float2half_rn(v.z), __float2half_rn(v.w));
    }
}

// ----------------------------------------------------------------------------
// Stage 2: exchange-scatter (one writer per unique pos, zero-restores aux)
// ----------------------------------------------------------------------------
__global__ void __launch_bounds__(256) scatter_kernel(
    const int* __restrict__ flip, const float* __restrict__ vals, int n) {
    const int base = (blockIdx.x * 256 + threadIdx.x) * 4;
    if (base + 3 < n) {
        const int4 f = *reinterpret_cast<const int4*>(flip + base);
        int pos[4] = {f.x, f.y, f.z, f.w}, old[4];
        #pragma unroll
        for (int k = 0; k < 4; ++k) old[k] = atomicExch(&g_aux[pos[k]], 0);
        #pragma unroll
        for (int k = 0; k < 4; ++k)
            if (old[k]) g_wh[pos[k]] = __float2half_rn(vals[old[k] - 1] * 0.1f);
    } else {
        for (int k = 0; k < 4; ++k)
            if (base + k < n) {
                int p = flip[base + k];
                int o = atomicExch(&g_aux[p], 0);
                if (o) g_wh[p] = __float2half_rn(vals[o - 1] * 0.1f);
            }
    }
}

// ============================================================================
// Stage 3: GEMM. CTA tile 128x64, K-chunk 128 (two 128B-row sub-tiles),
// TRIPLE-buffered cp.async with wait_group 1, one __syncthreads per chunk.
// ============================================================================
#define SW128(b) ((b) ^ (((b) >> 3) & 0x70))

static constexpr int A_SUB = 16384;   // one A sub-tile: 128 rows x 128B
static constexpr int B_OFF = 32768;   // A total 32KB, then B
static constexpr int B_SUB = 8192;    // one B sub-tile: 64 rows x 128B
static constexpr int BUF   = 49152;   // 48KB per chunk buffer
static constexpr int GEMM_SMEM = 3 * BUF;   // 144KB
static constexpr int NC    = I_DIM / 128;   // 32 K-chunks

__device__ __forceinline__ uint32_t smem_u32(const void* p) {
    uint32_t a;
    asm("{ .reg .u64 t; cvta.to.shared.u64 t, %1; cvt.u32.u64 %0, t; }"
        : "=r"(a) : "l"(p));
    return a;
}
__device__ __forceinline__ void cp16(uint32_t dst, const void* src) {
    asm volatile("cp.async.cg.shared.global [%0], [%1], 16;"
                 :: "r"(dst), "l"(src) : "memory");
}
__device__ __forceinline__ void cp_commit() {
    asm volatile("cp.async.commit_group;" ::: "memory");
}
__device__ __forceinline__ void cp_wait1() {
    asm volatile("cp.async.wait_group 1;" ::: "memory");
}
__device__ __forceinline__ void cp_wait0() {
    asm volatile("cp.async.wait_group 0;" ::: "memory");
}
__device__ __forceinline__ void ldsm4(uint32_t* r, uint32_t addr) {
    asm volatile("ldmatrix.sync.aligned.m8n8.x4.shared.b16 {%0,%1,%2,%3}, [%4];"
                 : "=r"(r[0]), "=r"(r[1]), "=r"(r[2]), "=r"(r[3]) : "r"(addr));
}
__device__ __forceinline__ void mma16816(float* c, const uint32_t* a,
                                         uint32_t b0, uint32_t b1) {
    asm volatile(
        "mma.sync.aligned.m16n8k16.row.col.f32.f16.f16.f32 "
        "{%0,%1,%2,%3}, {%4,%5,%6,%7}, {%8,%9}, {%0,%1,%2,%3};"
        : "+f"(c[0]), "+f"(c[1]), "+f"(c[2]), "+f"(c[3])
        : "r"(a[0]), "r"(a[1]), "r"(a[2]), "r"(a[3]), "r"(b0), "r"(b1));
}

// Load K-chunk c (128 cols) into buffer: A 128x256B as 2 sub-tiles, B 64x256B.
__device__ __forceinline__ void prefetch(uint32_t bufb, int c, int m0, int n0, int tid) {
    // A: thread -> row tid/2, sub-tile tid&1, 8 contiguous 16B vecs
    {
        const int row = tid >> 1, sub = tid & 1;
        const uint4* src = reinterpret_cast<const uint4*>(g_xh)
                         + (size_t)(m0 + row) * 512 + c * 16 + sub * 8;
        const uint32_t db = bufb + sub * A_SUB;
        const uint32_t rb = (uint32_t)row * 128;
        #pragma unroll
        for (int j = 0; j < 8; ++j)
            cp16(db + SW128(rb + j * 16), src + j);
    }
    // B: thread -> row tid/4, kvec group (tid&3)*4 .. +3
    {
        const int row = tid >> 2, kq = (tid & 3) * 4;
        const uint4* src = reinterpret_cast<const uint4*>(g_wh)
                         + (size_t)(n0 + row) * 512 + c * 16 + kq;
        const uint32_t rb = (uint32_t)row * 128;
        #pragma unroll
        for (int j = 0; j < 4; ++j) {
            const int kv = kq + j;
            cp16(bufb + B_OFF + (kv >> 3) * B_SUB + SW128(rb + (kv & 7) * 16),
                 src + j);
        }
    }
}

__global__ void __launch_bounds__(256, 1) gemm_kernel(float* __restrict__ y) {
    extern __shared__ __align__(1024) char smem[];
    const uint32_t sb = smem_u32(smem);
    const int tid = threadIdx.x, lane = tid & 31, wid = tid >> 5;
    const int wm = wid >> 1, wn = wid & 1;          // warp grid 4(M) x 2(N)
    const int n0 = blockIdx.x * 64;
    const int m0 = blockIdx.y * 128;

    float acc[2][4][4];
    #pragma unroll
    for (int i = 0; i < 2; ++i)
        #pragma unroll
        for (int j = 0; j < 4; ++j)
            #pragma unroll
            for (int q = 0; q < 4; ++q) acc[i][j][q] = 0.f;

    const int rl = lane & 15, kh = lane >> 4;
    const uint32_t arow0 = (uint32_t)(wm * 32 + rl) * 128;
    const uint32_t arow1 = arow0 + 16 * 128;
    const uint32_t brow0 = (uint32_t)(wn * 32 + rl) * 128;
    const uint32_t brow1 = brow0 + 16 * 128;

    prefetch(sb,       0, m0, n0, tid); cp_commit();
    prefetch(sb + BUF, 1, m0, n0, tid); cp_commit();

    for (int c = 0; c < NC; ++c) {
        if (c + 2 < NC) cp_wait1(); else cp_wait0();
        __syncthreads();   // all warps done with buf (c-1)%3 AND chunk c ready
        if (c + 2 < NC) {
            prefetch(sb + ((c + 2) % 3) * BUF, c + 2, m0, n0, tid);
            cp_commit();
        }
        const uint32_t bb = sb + (c % 3) * BUF;

        #pragma unroll
        for (int ks = 0; ks < 8; ++ks) {
            const uint32_t sub_a = bb + (ks >> 2) * A_SUB;
            const uint32_t sub_b = bb + B_OFF + (ks >> 2) * B_SUB;
            const uint32_t kb = (uint32_t)(ks & 3) * 32 + (uint32_t)kh * 16;
            uint32_t ah[2][4], bh[2][4];
            ldsm4(ah[0], sub_a + SW128(arow0 + kb));
            ldsm4(ah[1], sub_a + SW128(arow1 + kb));
            ldsm4(bh[0], sub_b + SW128(brow0 + kb));
            ldsm4(bh[1], sub_b + SW128(brow1 + kb));
            #pragma unroll
            for (int mi = 0; mi < 2; ++mi)
                #pragma unroll
                for (int nj = 0; nj < 2; ++nj) {
                    mma16816(acc[mi][nj*2+0], ah[mi], bh[nj][0], bh[nj][2]);
                    mma16816(acc[mi][nj*2+1], ah[mi], bh[nj][1], bh[nj][3]);
                }
        }
    }

    #pragma unroll
    for (int mi = 0; mi < 2; ++mi) {
        const int row0 = m0 + wm * 32 + mi * 16 + (lane >> 2);
        #pragma unroll
        for (int nb = 0; nb < 4; ++nb) {
            const int col = n0 + wn * 32 + nb * 8 + (lane & 3) * 2;
            *reinterpret_cast<float2*>(y + (size_t)row0 * O_DIM + col) =
                make_float2(acc[mi][nb][0], acc[mi][nb][1]);
            *reinterpret_cast<float2*>(y + (size_t)(row0 + 8) * O_DIM + col) =
                make_float2(acc[mi][nb][2], acc[mi][nb][3]);
        }
    }
}

// ============================================================================
extern "C" void kernel_launch(void* const* d_in, const int* in_sizes, int n_in,
                              void* d_out, int out_size) {
    const float* x    = (const float*)d_in[0];
    const float* w    = (const float*)d_in[1];
    const int*   flip = (const int*)d_in[2];   // JAX x64 disabled -> int32
    const float* vals = (const float*)d_in[3];
    float*       y    = (float*)d_out;
    const int nflip = in_sizes[2];

    stage1_kernel<<<NB_WIN + NB_CX + NB_CW, 256>>>(
        reinterpret_cast<const float4*>(x), reinterpret_cast<const float4*>(w),
        flip, nflip);
    scatter_kernel<<<(nflip + 1023) / 1024, 256>>>(flip, vals, nflip);

    cudaFuncSetAttribute(gemm_kernel, cudaFuncAttributeMaxDynamicSharedMemorySize,
                         GEMM_SMEM);
    gemm_kernel<<<dim3(O_DIM / 64, B_ROWS / 128, 1), 256, GEMM_SMEM>>>(y);
}

// round 8
// speedup vs baseline: 2.8183x; 1.3677x over previous
#include <cuda_runtime.h>
#include <cuda_fp16.h>
#include <cstdint>

// ============================================================================
// y = x @ W_mod^T ; W_mod = W with values*0.1 scattered at flip_idx (last wins)
// x:[256,4096] f32, W:[4096,4096] f32, flip:[1M] int32, vals:[1M] f32 -> y f32
// GEMM loads via 1D cp.async.bulk (TMA): stage1 stores x/W in chunk-major,
// PRE-SWIZZLED (SW128) tile images so each tile is ONE contiguous bulk copy.
// ============================================================================

#define O_DIM  4096
#define I_DIM  4096
#define B_ROWS 256
#define W_ELEMS (O_DIM * I_DIM)
#define X_ELEMS (B_ROWS * I_DIM)

#define SW128(b) ((b) ^ (((b) >> 3) & 0x70))

// Chunk-major swizzled layouts (K-chunk = 128 cols = 256B, two 128B sub-tiles):
//  g_xh: [chunk 32][m_tile 2][ sub0 16KB | sub1 16KB ]          (64KB/chunk)
//  g_wh: [chunk 32][n_tile 64][ sub0 8KB | sub1 8KB ]           (1MB/chunk)
__device__ __align__(16) __half g_xh[X_ELEMS];
__device__ __align__(16) __half g_wh[W_ELEMS];
// zero at module load; atomicExch in scatter restores all-zero every launch
__device__ int g_aux[W_ELEMS];

// ----------------------------------------------------------------------------
// Stage 1: fused [winner election | x convert | W convert] -> swizzled layout
// ----------------------------------------------------------------------------
static constexpr int NB_WIN = 977;                 // ceil(1e6/1024), 4 idx/thr
static constexpr int NB_CX  = X_ELEMS / 4 / 256;   // 1024
static constexpr int NB_CW  = W_ELEMS / 4 / 256;   // 16384

__global__ void __launch_bounds__(256) stage1_kernel(
    const float4* __restrict__ x, const float4* __restrict__ w,
    const int* __restrict__ flip, int n) {
    const int bid = blockIdx.x, tid = threadIdx.x;
    if (bid < NB_WIN) {
        const int base = bid * 1024 + tid * 4;
        if (base + 3 < n) {
            const int4 f = *reinterpret_cast<const int4*>(flip + base);
            atomicMax(&g_aux[f.x], base + 1);
            atomicMax(&g_aux[f.y], base + 2);
            atomicMax(&g_aux[f.z], base + 3);
            atomicMax(&g_aux[f.w], base + 4);
        } else {
            for (int k = 0; k < 4; ++k)
                if (base + k < n) atomicMax(&g_aux[flip[base + k]], base + k + 1);
        }
    } else if (bid < NB_WIN + NB_CX) {
        const int i = (bid - NB_WIN) * 256 + tid;
        const int m = i >> 10, kq = (i & 1023) << 2;      // 4 k-elems
        float4 v = x[i];
        uint2 p = make_uint2(
            (uint32_t)__half_as_ushort(__float2half_rn(v.x)) |
            ((uint32_t)__half_as_ushort(__float2half_rn(v.y)) << 16),
            (uint32_t)__half_as_ushort(__float2half_rn(v.z)) |
            ((uint32_t)__half_as_ushort(__float2half_rn(v.w)) << 16));
        const int c = kq >> 7, k0 = kq & 127, sub = k0 >> 6, kk = k0 & 63;
        char* dst = reinterpret_cast<char*>(g_xh)
                  + (size_t)c * 65536 + (m >> 7) * 32768 + sub * 16384
                  + SW128((m & 127) * 128 + kk * 2);
        *reinterpret_cast<uint2*>(dst) = p;
    } else {
        const int i = (bid - NB_WIN - NB_CX) * 256 + tid;
        const int o = i >> 10, kq = (i & 1023) << 2;
        float4 v = w[i];
        uint2 p = make_uint2(
            (uint32_t)__half_as_ushort(__float2half_rn(v.x)) |
            ((uint32_t)__half_as_ushort(__float2half_rn(v.y)) << 16),
            (uint32_t)__half_as_ushort(__float2half_rn(v.z)) |
            ((uint32_t)__half_as_ushort(__float2half_rn(v.w)) << 16));
        const int c = kq >> 7, k0 = kq & 127, sub = k0 >> 6, kk = k0 & 63;
        char* dst = reinterpret_cast<char*>(g_wh)
                  + (size_t)c * 1048576 + (o >> 6) * 16384 + sub * 8192
                  + SW128((o & 63) * 128 + kk * 2);
        *reinterpret_cast<uint2*>(dst) = p;
    }
}

// ----------------------------------------------------------------------------
// Stage 2: exchange-scatter into the swizzled W layout
// ----------------------------------------------------------------------------
__device__ __forceinline__ void scatter_one(int pos, float v) {
    const int o = pos >> 12, k = pos & 4095;
    const int c = k >> 7, k0 = k & 127, sub = k0 >> 6, kk = k0 & 63;
    char* dst = reinterpret_cast<char*>(g_wh)
              + (size_t)c * 1048576 + (o >> 6) * 16384 + sub * 8192
              + SW128((o & 63) * 128 + kk * 2);
    *reinterpret_cast<__half*>(dst) = __float2half_rn(v);
}

__global__ void __launch_bounds__(256) scatter_kernel(
    const int* __restrict__ flip, const float* __restrict__ vals, int n) {
    const int base = (blockIdx.x * 256 + threadIdx.x) * 4;
    if (base + 3 < n) {
        const int4 f = *reinterpret_cast<const int4*>(flip + base);
        int pos[4] = {f.x, f.y, f.z, f.w}, old[4];
        #pragma unroll
        for (int k = 0; k < 4; ++k) old[k] = atomicExch(&g_aux[pos[k]], 0);
        #pragma unroll
        for (int k = 0; k < 4; ++k)
            if (old[k]) scatter_one(pos[k], vals[old[k] - 1] * 0.1f);
    } else {
        for (int k = 0; k < 4; ++k)
            if (base + k < n) {
                int p = flip[base + k];
                int o = atomicExch(&g_aux[p], 0);
                if (o) scatter_one(p, vals[o - 1] * 0.1f);
            }
    }
}

// ============================================================================
// Stage 3: GEMM. CTA 128x64, K-chunk 128, 3-deep TMA bulk pipeline.
// ============================================================================
static constexpr int A_SUB = 16384;   // A sub-tile: 128 rows x 128B
static constexpr int B_OFF = 32768;
static constexpr int B_SUB = 8192;    // B sub-tile: 64 rows x 128B
static constexpr int BUF   = 49152;
static constexpr int SM_TILES = 1024; // mbarriers live below
static constexpr int GEMM_SMEM = SM_TILES + 3 * BUF;   // 148480
static constexpr int NC    = I_DIM / 128;   // 32 chunks

__device__ __forceinline__ uint32_t smem_u32(const void* p) {
    uint32_t a;
    asm("{ .reg .u64 t; cvta.to.shared.u64 t, %1; cvt.u32.u64 %0, t; }"
        : "=r"(a) : "l"(p));
    return a;
}
__device__ __forceinline__ void ldsm4(uint32_t* r, uint32_t addr) {
    asm volatile("ldmatrix.sync.aligned.m8n8.x4.shared.b16 {%0,%1,%2,%3}, [%4];"
                 : "=r"(r[0]), "=r"(r[1]), "=r"(r[2]), "=r"(r[3]) : "r"(addr));
}
__device__ __forceinline__ void mma16816(float* c, const uint32_t* a,
                                         uint32_t b0, uint32_t b1) {
    asm volatile(
        "mma.sync.aligned.m16n8k16.row.col.f32.f16.f16.f32 "
        "{%0,%1,%2,%3}, {%4,%5,%6,%7}, {%8,%9}, {%0,%1,%2,%3};"
        : "+f"(c[0]), "+f"(c[1]), "+f"(c[2]), "+f"(c[3])
        : "r"(a[0]), "r"(a[1]), "r"(a[2]), "r"(a[3]), "r"(b0), "r"(b1));
}

#define MBAR_WAIT(mbar_addr, phase) do {                                         \
    uint32_t _mbar = (uint32_t)(mbar_addr);                                      \
    uint32_t _parity = (uint32_t)(phase);                                        \
    uint32_t _done;                                                              \
    asm volatile(                                                                \
        "{\n\t.reg .pred p;\n\t"                                                 \
        "mbarrier.try_wait.parity.acquire.cta.shared::cta.b64 p, [%1], %2;\n\t"  \
        "selp.b32 %0, 1, 0, p;\n\t}"                                             \
        : "=r"(_done) : "r"(_mbar), "r"(_parity) : "memory");                    \
    if (!_done) {                                                                \
        asm volatile(                                                            \
            "{\n\t.reg .pred P1;\n\t"                                            \
            "WL_%=:\n\t"                                                         \
            "mbarrier.try_wait.parity.acquire.cta.shared::cta.b64 P1, [%0], %1, 0x989680;\n\t" \
            "@P1 bra.uni WD_%=;\n\t"                                             \
            "bra.uni WL_%=;\n\t"                                                 \
            "WD_%=:\n\t}"                                                        \
            :: "r"(_mbar), "r"(_parity) : "memory");                             \
    }                                                                            \
} while (0)

// Issue A(32KB) + B(16KB) bulk copies for chunk c into buffer (single thread).
__device__ __forceinline__ void tma_chunk(uint32_t bufb, uint32_t mbar,
                                          int c, int m0, int n0) {
    asm volatile("mbarrier.arrive.expect_tx.shared.b64 _, [%0], %1;"
                 :: "r"(mbar), "r"(49152u) : "memory");
    const char* srcA = reinterpret_cast<const char*>(g_xh)
                     + (size_t)c * 65536 + (m0 >> 7) * 32768;
    const char* srcB = reinterpret_cast<const char*>(g_wh)
                     + (size_t)c * 1048576 + (n0 >> 6) * 16384;
    asm volatile(
        "cp.async.bulk.shared::cluster.global.mbarrier::complete_tx::bytes "
        "[%0], [%1], %2, [%3];"
        :: "r"(bufb), "l"(srcA), "r"(32768u), "r"(mbar) : "memory");
    asm volatile(
        "cp.async.bulk.shared::cluster.global.mbarrier::complete_tx::bytes "
        "[%0], [%1], %2, [%3];"
        :: "r"(bufb + B_OFF), "l"(srcB), "r"(16384u), "r"(mbar) : "memory");
}

__global__ void __launch_bounds__(256, 1) gemm_kernel(float* __restrict__ y) {
    extern __shared__ __align__(1024) char smem[];
    const uint32_t sb = smem_u32(smem);
    const int tid = threadIdx.x, lane = tid & 31, wid = tid >> 5;
    const int wm = wid >> 1, wn = wid & 1;          // warp grid 4(M) x 2(N)
    const int n0 = blockIdx.x * 64;
    const int m0 = blockIdx.y * 128;

    if (tid == 0) {
        asm volatile("mbarrier.init.shared.b64 [%0], 1;" :: "r"(sb + 0) : "memory");
        asm volatile("mbarrier.init.shared.b64 [%0], 1;" :: "r"(sb + 8) : "memory");
        asm volatile("mbarrier.init.shared.b64 [%0], 1;" :: "r"(sb + 16) : "memory");
    }
    __syncthreads();
    if (tid == 0) {
        tma_chunk(sb + SM_TILES + 0 * BUF, sb + 0,  0, m0, n0);
        tma_chunk(sb + SM_TILES + 1 * BUF, sb + 8,  1, m0, n0);
        tma_chunk(sb + SM_TILES + 2 * BUF, sb + 16, 2, m0, n0);
    }

    float acc[2][4][4];
    #pragma unroll
    for (int i = 0; i < 2; ++i)
        #pragma unroll
        for (int j = 0; j < 4; ++j)
            #pragma unroll
            for (int q = 0; q < 4; ++q) acc[i][j][q] = 0.f;

    const int rl = lane & 15, kh = lane >> 4;
    const uint32_t arow0 = (uint32_t)(wm * 32 + rl) * 128;
    const uint32_t arow1 = arow0 + 16 * 128;
    const uint32_t brow0 = (uint32_t)(wn * 32 + rl) * 128;
    const uint32_t brow1 = brow0 + 16 * 128;

    for (int c = 0; c < NC; ++c) {
        const int b = c % 3;
        MBAR_WAIT(sb + b * 8, (c / 3) & 1);
        const uint32_t bb = sb + SM_TILES + b * BUF;

        #pragma unroll
        for (int ks = 0; ks < 8; ++ks) {
            const uint32_t sub_a = bb + (ks >> 2) * A_SUB;
            const uint32_t sub_b = bb + B_OFF + (ks >> 2) * B_SUB;
            const uint32_t kb = (uint32_t)(ks & 3) * 32 + (uint32_t)kh * 16;
            uint32_t ah[2][4], bh[2][4];
            ldsm4(ah[0], sub_a + SW128(arow0 + kb));
            ldsm4(ah[1], sub_a + SW128(arow1 + kb));
            ldsm4(bh[0], sub_b + SW128(brow0 + kb));
            ldsm4(bh[1], sub_b + SW128(brow1 + kb));
            #pragma unroll
            for (int mi = 0; mi < 2; ++mi)
                #pragma unroll
                for (int nj = 0; nj < 2; ++nj) {
                    mma16816(acc[mi][nj*2+0], ah[mi], bh[nj][0], bh[nj][2]);
                    mma16816(acc[mi][nj*2+1], ah[mi], bh[nj][1], bh[nj][3]);
                }
        }
        __syncthreads();   // all warps done with buffer b
        if (tid == 0 && c + 3 < NC)
            tma_chunk(sb + SM_TILES + b * BUF, sb + b * 8, c + 3, m0, n0);
    }

    #pragma unroll
    for (int mi = 0; mi < 2; ++mi) {
        const int row0 = m0 + wm * 32 + mi * 16 + (lane >> 2);
        #pragma unroll
        for (int nb = 0; nb < 4; ++nb) {
            const int col = n0 + wn * 32 + nb * 8 + (lane & 3) * 2;
            *reinterpret_cast<float2*>(y + (size_t)row0 * O_DIM + col) =
                make_float2(acc[mi][nb][0], acc[mi][nb][1]);
            *reinterpret_cast<float2*>(y + (size_t)(row0 + 8) * O_DIM + col) =
                make_float2(acc[mi][nb][2], acc[mi][nb][3]);
        }
    }
}

// ============================================================================
extern "C" void kernel_launch(void* const* d_in, const int* in_sizes, int n_in,
                              void* d_out, int out_size) {
    const float* x    = (const float*)d_in[0];
    const float* w    = (const float*)d_in[1];
    const int*   flip = (const int*)d_in[2];   // JAX x64 disabled -> int32
    const float* vals = (const float*)d_in[3];
    float*       y    = (float*)d_out;
    const int nflip = in_sizes[2];

    stage1_kernel<<<NB_WIN + NB_CX + NB_CW, 256>>>(
        reinterpret_cast<const float4*>(x), reinterpret_cast<const float4*>(w),
        flip, nflip);
    scatter_kernel<<<(nflip + 1023) / 1024, 256>>>(flip, vals, nflip);

    cudaFuncSetAttribute(gemm_kernel, cudaFuncAttributeMaxDynamicSharedMemorySize,
                         GEMM_SMEM);
    gemm_kernel<<<dim3(O_DIM / 64, B_ROWS / 128, 1), 256, GEMM_SMEM>>>(y);
}